// round 17
// baseline (speedup 1.0000x reference)
#include <cuda_runtime.h>
#include <cstdint>

#define DIMK 1024
#define BSZ  2
#define SEQ  4096
#define H    16
#define HD   64
#define M_TOT (BSZ * SEQ)   // 8192

// ---------------------------------------------------------------------------
// Scratch. tf32 bit patterns as u32.
// g_q/g_k: d perm8 (attn layout). g_v: plain. g_att/g_x32/g_w32: k perm16
// (gemm LDS.128 fragment layout).
// perm8(k)  = ((k&3)<<1)|((k&4)>>2)                       (pairs adjacent)
// perm16(k) = ((k&3)<<2)|((k&4)>>2)|(((k&8)>>3)<<1)       (quads adjacent)
// ---------------------------------------------------------------------------
__device__ uint32_t g_q[(size_t)BSZ * H * SEQ * HD];
__device__ uint32_t g_k[(size_t)BSZ * H * SEQ * HD];
__device__ uint32_t g_v[(size_t)BSZ * H * SEQ * HD];
__device__ uint32_t g_att[(size_t)BSZ * SEQ * DIMK];
__device__ uint32_t g_x32[(size_t)M_TOT * DIMK];
__device__ uint32_t g_w32[4][(size_t)DIMK * DIMK];

__device__ __forceinline__ int perm8(int k)  { return ((k & 3) << 1) | ((k & 4) >> 2); }
__device__ __forceinline__ int perm16(int k) {
    return ((k & 3) << 2) | ((k & 4) >> 2) | (((k & 8) >> 3) << 1);
}

__device__ __forceinline__ uint32_t f32_tf32(float f) {
    uint32_t r; asm("cvt.rna.tf32.f32 %0, %1;" : "=r"(r) : "f"(f)); return r;
}
__device__ __forceinline__ float ex2f(float x) {
    float r; asm("ex2.approx.f32 %0, %1;" : "=f"(r) : "f"(x)); return r;
}
__device__ __forceinline__ uint32_t smem_u32(const void* p) {
    uint32_t a;
    asm("{ .reg .u64 t; cvta.to.shared.u64 t, %1; cvt.u32.u64 %0, t; }" : "=r"(a) : "l"(p));
    return a;
}
__device__ __forceinline__ void cp16(uint32_t s, const void* g) {
    asm volatile("cp.async.cg.shared.global [%0], [%1], 16;" :: "r"(s), "l"(g));
}
#define CP_COMMIT()  asm volatile("cp.async.commit_group;" ::: "memory")
#define CP_WAIT(n)   asm volatile("cp.async.wait_group %0;" :: "n"(n) : "memory")

__device__ __forceinline__ void mma_tf32(float& c0, float& c1, float& c2, float& c3,
                                         uint32_t a0, uint32_t a1, uint32_t a2, uint32_t a3,
                                         uint32_t b0, uint32_t b1) {
    asm volatile("mma.sync.aligned.m16n8k8.row.col.f32.tf32.tf32.f32 "
        "{%0,%1,%2,%3}, {%4,%5,%6,%7}, {%8,%9}, {%0,%1,%2,%3};"
        : "+f"(c0), "+f"(c1), "+f"(c2), "+f"(c3)
        : "r"(a0), "r"(a1), "r"(a2), "r"(a3), "r"(b0), "r"(b1));
}

// ---------------------------------------------------------------------------
// fp32 -> tf32 with perm16 (gemm input layout).
// ---------------------------------------------------------------------------
__device__ __forceinline__ void conv4(const float* __restrict__ src,
                                      uint32_t* __restrict__ dst, int i) {
    float4 v = ((const float4*)src)[i];
    const int c    = i << 2;
    const int base = c & ~15;
    const int off  = (c >> 2) & 3;
    dst[base + off + 0]  = f32_tf32(v.x);
    dst[base + off + 4]  = f32_tf32(v.y);
    dst[base + off + 8]  = f32_tf32(v.z);
    dst[base + off + 12] = f32_tf32(v.w);
}

__global__ void __launch_bounds__(256) conv_x(const float* __restrict__ src,
                                              uint32_t* __restrict__ dst, int n4)
{
    const int i = blockIdx.x * blockDim.x + threadIdx.x;
    if (i < n4) conv4(src, dst, i);
}

__global__ void __launch_bounds__(256) conv_w(const float* __restrict__ s0,
                                              const float* __restrict__ s1,
                                              const float* __restrict__ s2,
                                              const float* __restrict__ s3,
                                              uint32_t* __restrict__ dst)
{
    const int z = blockIdx.y;
    const float* src = (z == 0) ? s0 : (z == 1) ? s1 : (z == 2) ? s2 : s3;
    const int i = blockIdx.x * blockDim.x + threadIdx.x;
    conv4(src, dst + (size_t)z * DIMK * DIMK, i);
}

// ---------------------------------------------------------------------------
// tf32 mma.sync GEMM: CTA 128x128, 256 thr, 8 warps (2M x 4N), warp 64x32.
// 2-stage cp.async, perm16 LDS.128 fragment loads.
// KST=48 (≡16 mod 32): quarter-warp LDS.128 phases bank-disjoint.
// Q/K epilogue scatters d in perm8 (attn layout, 32B-sector-local).
// ---------------------------------------------------------------------------
#define BM 128
#define BN 128
#define BK 32
#define KST 48
#define STGW ((BM + BN) * KST)           // 12288 words / stage
#define SM_GEMM (2 * STGW * 4)           // 98304 B -> 2 CTAs/SM

__global__ void __launch_bounds__(256, 2) gemm_mma(const uint32_t* __restrict__ A,
                                                   const uint32_t* __restrict__ W0,
                                                   const uint32_t* __restrict__ W1,
                                                   const uint32_t* __restrict__ W2,
                                                   const float* __restrict__ b0p,
                                                   const float* __restrict__ b1p,
                                                   const float* __restrict__ b2p,
                                                   uint32_t* __restrict__ C0,
                                                   uint32_t* __restrict__ C1,
                                                   uint32_t* __restrict__ C2,
                                                   float* __restrict__ Cf,
                                                   int layout)
{
    extern __shared__ __align__(16) uint32_t gsm[];

    const int z = blockIdx.z;
    const uint32_t* W    = (z == 0) ? W0 : (z == 1) ? W1 : W2;
    const float*    bias = (z == 0) ? b0p : (z == 1) ? b1p : b2p;
    uint32_t*       C    = (z == 0) ? C0 : (z == 1) ? C1 : C2;

    const int tid  = threadIdx.x;
    const int wid  = tid >> 5;
    const int lane = tid & 31;
    const int g    = lane >> 2;
    const int t    = lane & 3;
    const int wm   = wid & 1;
    const int wn   = wid >> 1;
    const int m0   = blockIdx.y * BM;
    const int n0   = blockIdx.x * BN;

    const int lrow = tid >> 3;        // 0..31
    const int lc4  = (tid & 7) << 2;  // 0..28 step 4

    const uint32_t smb = smem_u32(gsm);

    float acc[4][4][4];
#pragma unroll
    for (int i = 0; i < 4; i++)
#pragma unroll
        for (int j = 0; j < 4; j++)
#pragma unroll
            for (int r = 0; r < 4; r++) acc[i][j][r] = 0.f;

    const int warpAm = wm * 64;
    const int warpBn = wn * 32;

    const uint32_t* Abase = A + (size_t)(m0 + lrow) * DIMK + lc4;
    const uint32_t* Wbase = W + (size_t)(n0 + lrow) * DIMK + lc4;
    const uint32_t sAoff  = smb + (uint32_t)(lrow * KST + lc4) * 4;
    const uint32_t sBoff  = sAoff + (uint32_t)(BM * KST) * 4;

    // prologue: chunk 0 into stage 0
#pragma unroll
    for (int it = 0; it < 4; it++) {
        const int ro = it << 5;
        cp16(sAoff + (uint32_t)(ro * KST) * 4, Abase + (size_t)ro * DIMK);
        cp16(sBoff + (uint32_t)(ro * KST) * 4, Wbase + (size_t)ro * DIMK);
    }
    CP_COMMIT();

    for (int c = 0; c < 32; c++) {
        CP_WAIT(0);
        __syncthreads();

        if (c < 31) {
            const uint32_t sb = ((c + 1) & 1) * (uint32_t)(STGW * 4);
            const int k0 = (c + 1) * BK;
#pragma unroll
            for (int it = 0; it < 4; it++) {
                const int ro = it << 5;
                cp16(sAoff + sb + (uint32_t)(ro * KST) * 4, Abase + (size_t)ro * DIMK + k0);
                cp16(sBoff + sb + (uint32_t)(ro * KST) * 4, Wbase + (size_t)ro * DIMK + k0);
            }
            CP_COMMIT();
        }

        const uint32_t* As = gsm + (c & 1) * STGW;
        const uint32_t* Bs = As + BM * KST;

#pragma unroll
        for (int hh = 0; hh < 2; hh++) {       // two k16 groups per BK=32
            const int kw = (hh << 4) + (t << 2);
            uint4 alo[4], ahi[4], bfr[4];
#pragma unroll
            for (int mt = 0; mt < 4; mt++) {
                const int rb = warpAm + (mt << 4);
                alo[mt] = *(const uint4*)&As[(rb + g    ) * KST + kw];
                ahi[mt] = *(const uint4*)&As[(rb + g + 8) * KST + kw];
            }
#pragma unroll
            for (int nt = 0; nt < 4; nt++) {
                const int nb = warpBn + (nt << 3);
                bfr[nt] = *(const uint4*)&Bs[(nb + g) * KST + kw];
            }
#pragma unroll
            for (int mt = 0; mt < 4; mt++)
#pragma unroll
                for (int nt = 0; nt < 4; nt++) {
                    mma_tf32(acc[mt][nt][0], acc[mt][nt][1],
                             acc[mt][nt][2], acc[mt][nt][3],
                             alo[mt].x, ahi[mt].x, alo[mt].y, ahi[mt].y,
                             bfr[nt].x, bfr[nt].y);
                    mma_tf32(acc[mt][nt][0], acc[mt][nt][1],
                             acc[mt][nt][2], acc[mt][nt][3],
                             alo[mt].z, ahi[mt].z, alo[mt].w, ahi[mt].w,
                             bfr[nt].z, bfr[nt].w);
                }
        }
    }

#pragma unroll
    for (int nt = 0; nt < 4; nt++) {
        const int n = n0 + warpBn + (nt << 3) + (t << 1);
        const float bx = bias[n], by = bias[n + 1];
#pragma unroll
        for (int mt = 0; mt < 4; mt++) {
            const int r0 = m0 + warpAm + (mt << 4) + g;
            const int r1 = r0 + 8;
            const float v00 = acc[mt][nt][0] + bx, v01 = acc[mt][nt][1] + by;
            const float v10 = acc[mt][nt][2] + bx, v11 = acc[mt][nt][3] + by;
            if (layout == 0) {
                *(float2*)(Cf + (size_t)r0 * DIMK + n) = make_float2(v00, v01);
                *(float2*)(Cf + (size_t)r1 * DIMK + n) = make_float2(v10, v11);
            } else {
                const int h_ = n >> 6, d_ = n & 63;
                const int b0_ = r0 >> 12, s0_ = r0 & 4095;
                const int b1_ = r1 >> 12, s1_ = r1 & 4095;
                uint32_t* p0 = C + (((size_t)(b0_ * H + h_)) * SEQ + s0_) * HD;
                uint32_t* p1 = C + (((size_t)(b1_ * H + h_)) * SEQ + s1_) * HD;
                if (z < 2) {   // Q,K: perm8 d (attn layout)
                    const int pc0 = (d_ & ~7) | perm8(d_ & 7);
                    const int pc1 = (d_ & ~7) | perm8((d_ & 7) + 1);
                    p0[pc0] = f32_tf32(v00); p0[pc1] = f32_tf32(v01);
                    p1[pc0] = f32_tf32(v10); p1[pc1] = f32_tf32(v11);
                } else {       // V: unpermuted
                    *(uint2*)(p0 + d_) = make_uint2(f32_tf32(v00), f32_tf32(v01));
                    *(uint2*)(p1 + d_) = make_uint2(f32_tf32(v10), f32_tf32(v11));
                }
            }
        }
    }
}

// ---------------------------------------------------------------------------
// Tensorized sliding-window attention — R13 body (proven 156.6us):
// 64-query CTA, 128 thr, 4 warps, Q-frag hoist, Ps aliases dead Qs,
// boundary-only masking, perm8 LDS.64 fragments.
// ONLY change: epilogue writes g_att at perm16 d positions (O-proj layout).
// ---------------------------------------------------------------------------
#define AST 72
#define VST 68
#define SMEM_AMMA ((2 * 64 * AST + 64 * VST) * 4)   // 54272 B -> 4 CTAs/SM

__global__ void __launch_bounds__(128, 4) attn_mma()
{
    extern __shared__ __align__(16) uint32_t smu[];
    uint32_t* Qs = smu;                  // [64][AST]; dead after hoist -> Ps
    uint32_t* Ks = smu + 64 * AST;       // [64][AST]
    uint32_t* Vs = smu + 2 * 64 * AST;   // [64][VST] row-permuted

    const int tid  = threadIdx.x;
    const int w    = tid >> 5;
    const int lane = tid & 31;
    const int g    = lane >> 2;
    const int t    = lane & 3;

    const int qi = blockIdx.x & 63;
    const int h  = (blockIdx.x >> 6) & 15;
    const int b  = blockIdx.x >> 10;
    const int p0 = qi << 6;

    const size_t headoff = ((size_t)(b * H + h)) * SEQ * HD;
    const uint32_t* qbase = g_q + headoff;
    const uint32_t* kbase = g_k + headoff;
    const uint32_t* vbase = g_v + headoff;

    const uint32_t smb = smem_u32(smu);
    const uint32_t Ksb = smb + (uint32_t)(64 * AST) * 4;
    const uint32_t Vsb = smb + (uint32_t)(2 * 64 * AST) * 4;

    // stage Q, hoist this warp's fragments
#pragma unroll
    for (int it = 0; it < 8; it++) {
        const int u = tid + (it << 7);
        const int row = u >> 4, c4 = (u & 15) << 2;
        cp16(smb + (uint32_t)(row * AST + c4) * 4, qbase + (size_t)(p0 + row) * HD + c4);
    }
    CP_COMMIT(); CP_WAIT(0);
    __syncthreads();

    const int r0 = (w << 4) + g;
    const int q0 = p0 + r0;
    const int q1 = q0 + 8;
    const int pc0 = perm8(t << 1);
    const int pc1 = perm8((t << 1) + 1);

    uint2 qfl[8], qfh[8];
#pragma unroll
    for (int ks = 0; ks < 8; ks++) {
        const int kk = (ks << 3) + (t << 1);
        qfl[ks] = *(const uint2*)&Qs[r0 * AST + kk];
        qfh[ks] = *(const uint2*)&Qs[(r0 + 8) * AST + kk];
    }
    __syncthreads();   // Qs dead -> Ps
    uint32_t* Ps = Qs;

    float O[8][4];
#pragma unroll
    for (int nt = 0; nt < 8; nt++)
#pragma unroll
        for (int r = 0; r < 4; r++) O[nt][r] = 0.f;
    float m0 = -1.0e4f, m1 = -1.0e4f, l0 = 0.f, l1 = 0.f;

    const float SC = 0.125f * 1.44269504f;   // hd^-0.5 * log2(e)

    const int ktlo = (qi >= 8) ? (qi - 8) : 0;
    for (int kt = ktlo; kt <= qi; kt++) {
        const int t0 = kt << 6;
        const bool boundary = (kt == qi) || (kt == qi - 8);

        __syncthreads();
#pragma unroll
        for (int it = 0; it < 8; it++) {
            const int u = tid + (it << 7);
            const int row = u >> 4, c4 = (u & 15) << 2;
            const int pr = (row & ~7) | perm8(row & 7);   // V row permutation
            cp16(Ksb + (uint32_t)(row * AST + c4) * 4, kbase + (size_t)(t0 + row) * HD + c4);
            cp16(Vsb + (uint32_t)(pr  * VST + c4) * 4, vbase + (size_t)(t0 + row) * HD + c4);
        }
        CP_COMMIT(); CP_WAIT(0);
        __syncthreads();

        // S = Q K^T
        float s[8][4];
#pragma unroll
        for (int nt = 0; nt < 8; nt++)
#pragma unroll
            for (int r = 0; r < 4; r++) s[nt][r] = 0.f;

#pragma unroll
        for (int ks = 0; ks < 8; ks++) {
            const int kk = (ks << 3) + (t << 1);
#pragma unroll
            for (int nt = 0; nt < 8; nt++) {
                const uint2 kb = *(const uint2*)&Ks[((nt << 3) + g) * AST + kk];
                mma_tf32(s[nt][0], s[nt][1], s[nt][2], s[nt][3],
                         qfl[ks].x, qfh[ks].x, qfl[ks].y, qfh[ks].y, kb.x, kb.y);
            }
        }

        // scale (+ mask on boundary tiles) + online softmax
        float rmax0 = -3.0e4f, rmax1 = -3.0e4f;
        if (boundary) {
#pragma unroll
            for (int nt = 0; nt < 8; nt++) {
                const int c = t0 + (nt << 3) + (t << 1);
                s[nt][0] = ((unsigned)(q0 - c)     < 512u) ? s[nt][0] * SC : -3.0e4f;
                s[nt][1] = ((unsigned)(q0 - c - 1) < 512u) ? s[nt][1] * SC : -3.0e4f;
                s[nt][2] = ((unsigned)(q1 - c)     < 512u) ? s[nt][2] * SC : -3.0e4f;
                s[nt][3] = ((unsigned)(q1 - c - 1) < 512u) ? s[nt][3] * SC : -3.0e4f;
                rmax0 = fmaxf(rmax0, fmaxf(s[nt][0], s[nt][1]));
                rmax1 = fmaxf(rmax1, fmaxf(s[nt][2], s[nt][3]));
            }
        } else {
#pragma unroll
            for (int nt = 0; nt < 8; nt++) {
                s[nt][0] *= SC; s[nt][1] *= SC;
                s[nt][2] *= SC; s[nt][3] *= SC;
                rmax0 = fmaxf(rmax0, fmaxf(s[nt][0], s[nt][1]));
                rmax1 = fmaxf(rmax1, fmaxf(s[nt][2], s[nt][3]));
            }
        }
        rmax0 = fmaxf(rmax0, __shfl_xor_sync(0xffffffffu, rmax0, 1));
        rmax0 = fmaxf(rmax0, __shfl_xor_sync(0xffffffffu, rmax0, 2));
        rmax1 = fmaxf(rmax1, __shfl_xor_sync(0xffffffffu, rmax1, 1));
        rmax1 = fmaxf(rmax1, __shfl_xor_sync(0xffffffffu, rmax1, 2));

        const float mn0 = fmaxf(m0, rmax0);
        const float mn1 = fmaxf(m1, rmax1);
        const float al0 = ex2f(m0 - mn0);
        const float al1 = ex2f(m1 - mn1);
        m0 = mn0; m1 = mn1;

        float rs0 = 0.f, rs1 = 0.f;
#pragma unroll
        for (int nt = 0; nt < 8; nt++) {
            const float p00 = ex2f(s[nt][0] - mn0);
            const float p01 = ex2f(s[nt][1] - mn0);
            const float p10 = ex2f(s[nt][2] - mn1);
            const float p11 = ex2f(s[nt][3] - mn1);
            rs0 += p00 + p01;
            rs1 += p10 + p11;
            const int nb = nt << 3;
            Ps[r0 * AST + nb + pc0]       = f32_tf32(p00);
            Ps[r0 * AST + nb + pc1]       = f32_tf32(p01);
            Ps[(r0 + 8) * AST + nb + pc0] = f32_tf32(p10);
            Ps[(r0 + 8) * AST + nb + pc1] = f32_tf32(p11);
        }
        rs0 += __shfl_xor_sync(0xffffffffu, rs0, 1);
        rs0 += __shfl_xor_sync(0xffffffffu, rs0, 2);
        rs1 += __shfl_xor_sync(0xffffffffu, rs1, 1);
        rs1 += __shfl_xor_sync(0xffffffffu, rs1, 2);

        l0 = l0 * al0 + rs0;
        l1 = l1 * al1 + rs1;
#pragma unroll
        for (int nt = 0; nt < 8; nt++) {
            O[nt][0] *= al0; O[nt][1] *= al0;
            O[nt][2] *= al1; O[nt][3] *= al1;
        }
        __syncwarp();      // Ps rows are warp-private

        // O += P V
#pragma unroll
        for (int ks = 0; ks < 8; ks++) {
            const int kk = (ks << 3) + (t << 1);
            const uint2 pl = *(const uint2*)&Ps[r0 * AST + kk];
            const uint2 ph = *(const uint2*)&Ps[(r0 + 8) * AST + kk];
#pragma unroll
            for (int nt = 0; nt < 8; nt++) {
                const uint32_t b0 = Vs[kk * VST + (nt << 3) + g];
                const uint32_t b1 = Vs[(kk + 1) * VST + (nt << 3) + g];
                mma_tf32(O[nt][0], O[nt][1], O[nt][2], O[nt][3],
                         pl.x, ph.x, pl.y, ph.y, b0, b1);
            }
        }
    }

    // epilogue: normalize, write g_att at perm16 d positions (O-proj layout)
    const float inv0 = 1.f / l0;
    const float inv1 = 1.f / l1;
    uint32_t* dst0 = g_att + ((size_t)b * SEQ + q0) * DIMK + h * HD;
    uint32_t* dst1 = g_att + ((size_t)b * SEQ + q1) * DIMK + h * HD;
#pragma unroll
    for (int nt = 0; nt < 8; nt++) {
        const int w16  = (nt >> 1) << 4;
        const int c16a = ((nt & 1) << 3) + (t << 1);
        const int pa = w16 + perm16(c16a);
        const int pb = w16 + perm16(c16a + 1);
        dst0[pa] = f32_tf32(O[nt][0] * inv0);
        dst0[pb] = f32_tf32(O[nt][1] * inv0);
        dst1[pa] = f32_tf32(O[nt][2] * inv1);
        dst1[pb] = f32_tf32(O[nt][3] * inv1);
    }
}

// ---------------------------------------------------------------------------
extern "C" void kernel_launch(void* const* d_in, const int* in_sizes, int n_in,
                              void* d_out, int out_size)
{
    const float* x  = (const float*)d_in[0];
    const float* Wq = (const float*)d_in[1];
    const float* bq = (const float*)d_in[2];
    const float* Wk = (const float*)d_in[3];
    const float* bk = (const float*)d_in[4];
    const float* Wv = (const float*)d_in[5];
    const float* bv = (const float*)d_in[6];
    const float* Wo = (const float*)d_in[7];
    const float* bo = (const float*)d_in[8];
    float* out = (float*)d_out;

    uint32_t *qp, *kp, *vp, *ap, *xp, *wp;
    cudaGetSymbolAddress((void**)&qp, g_q);
    cudaGetSymbolAddress((void**)&kp, g_k);
    cudaGetSymbolAddress((void**)&vp, g_v);
    cudaGetSymbolAddress((void**)&ap, g_att);
    cudaGetSymbolAddress((void**)&xp, g_x32);
    cudaGetSymbolAddress((void**)&wp, g_w32);
    uint32_t* w0 = wp;
    uint32_t* w1 = wp + (size_t)DIMK * DIMK;
    uint32_t* w2 = wp + 2 * (size_t)DIMK * DIMK;
    uint32_t* w3 = wp + 3 * (size_t)DIMK * DIMK;

    cudaFuncSetAttribute(gemm_mma,
                         cudaFuncAttributeMaxDynamicSharedMemorySize, SM_GEMM);
    cudaFuncSetAttribute(attn_mma,
                         cudaFuncAttributeMaxDynamicSharedMemorySize, SMEM_AMMA);

    // pre-convert (perm16) x and all weights
    const int nx4 = M_TOT * DIMK / 4;
    const int nw4 = DIMK * DIMK / 4;
    conv_x<<<(nx4 + 255) / 256, 256>>>(x, xp, nx4);
    dim3 gw(nw4 / 256, 4);
    conv_w<<<gw, 256>>>(Wq, Wk, Wv, Wo, wp);

    dim3 gqkv(DIMK / BN, M_TOT / BM, 3);   // fused Q/K/V projections
    gemm_mma<<<gqkv, 256, SM_GEMM>>>(xp, w0, w1, w2, bq, bk, bv,
                                     qp, kp, vp, nullptr, 1);
    attn_mma<<<BSZ * H * (SEQ / 64), 128, SMEM_AMMA>>>();   // 2048 CTAs
    dim3 go(DIMK / BN, M_TOT / BM, 1);     // output projection (fp32 out)
    gemm_mma<<<go, 256, SM_GEMM>>>(ap, w3, w3, w3, bo, bo, bo,
                                   nullptr, nullptr, nullptr, out, 0);
}